// round 11
// baseline (speedup 1.0000x reference)
#include <cuda_runtime.h>
#include <math.h>

#define RIR_LENGTH 3968
#define PAD        40
#define BATCH      128
#define MAXO       15
#define GRID_TOT   29791
#define NIMG       4991          // |x|+|y|+|z| <= 15 lattice points
#define FSR        46.64723032f  // fp32(16000/343)
#define INV_PI     0.3183098862f

#define DIMAX      4007          // di <= 4007 <=> lowest tap bin <= 3967
#define BSH        2             // bucket = 4 delay-bins
#define NBUCK      1002          // ceil(4008/4)
#define MAXE       4992
#define EPAD       512           // sentinel pad (covers worst-case group scan)
#define ESTRIDE    (MAXE + EPAD)
#define WMAX       64
#define SPMAX      32
#define TPB        1024
#define GITER      ((GRID_TOT + TPB - 1) / TPB)  // 30

__device__ float4 g_ent[BATCH * ESTRIDE];
__device__ int    g_baseG[BATCH][NBUCK + 1];
__device__ float4 g_wrapG[BATCH][WMAX * 2];
__device__ int    g_spkiG[BATCH][SPMAX];
__device__ float  g_spkaG[BATCH][SPMAX];
__device__ int    g_nspG[BATCH];
__device__ int    g_nwrG[BATCH];

// ---------------------------------------------------------------------------
// Prep: per-batch image enumeration, bucket sort, entry finalization -> global
__global__ __launch_bounds__(TPB) void k_prep(const float* __restrict__ inp,
                                              float* __restrict__ out) {
    extern __shared__ __align__(16) char dynsm[];
    float2* sCache = (float2*)dynsm;                 // [MAXE]

    __shared__ float sPW[16], sPL[9], sPH[9], sGeo[9];
    __shared__ int   hist[NBUCK], base[NBUCK + 1], cur[NBUCK];
    __shared__ int   segbase[33];
    __shared__ int   s_icnt, s_nsp, s_nwr;

    const int b    = blockIdx.x;
    const int tid  = threadIdx.x;
    const int lane = tid & 31;

    for (int k = tid; k < NBUCK; k += TPB) hist[k] = 0;
    if (tid == 0) {
        s_icnt = 0; s_nsp = 0; s_nwr = 0;
        const float* r = inp + b * 12;
        float rx = r[0], ry = r[1], rz = r[2];
        sGeo[0] = rx;                  sGeo[1] = ry;                  sGeo[2] = rz;
        sGeo[3] = __fmul_rn(r[3], rx); sGeo[4] = __fmul_rn(r[4], ry); sGeo[5] = __fmul_rn(r[5], rz);
        sGeo[6] = __fmul_rn(r[6], rx); sGeo[7] = __fmul_rn(r[7], ry); sGeo[8] = __fmul_rn(r[8], rz);
        float aw  = __fadd_rn(__fmul_rn(r[9],  0.84f), 0.01f);
        float a4  = __fadd_rn(__fmul_rn(r[10], 0.84f), 0.01f);
        float a5  = __fadd_rn(__fmul_rn(r[11], 0.84f), 0.01f);
        double trw = sqrt(1.0 - (double)aw);
        double tr4 = sqrt(1.0 - (double)a4);
        double tr5 = sqrt(1.0 - (double)a5);
        double p = 1.0;
        for (int e = 0; e < 16; e++) { sPW[e] = (float)p; p *= trw; }
        p = 1.0;
        for (int e = 0; e < 9;  e++) { sPL[e] = (float)p; p *= tr4; }
        p = 1.0;
        for (int e = 0; e < 9;  e++) { sPH[e] = (float)p; p *= tr5; }
        // toa
        float dx = __fsub_rn(__fmul_rn(r[3], rx), __fmul_rn(r[6], rx));
        float dy = __fsub_rn(__fmul_rn(r[4], ry), __fmul_rn(r[7], ry));
        float dz = __fsub_rn(__fmul_rn(r[5], rz), __fmul_rn(r[8], rz));
        float ssq = __fadd_rn(__fadd_rn(__fmul_rn(dx, dx), __fmul_rn(dy, dy)),
                              __fmul_rn(dz, dz));
        out[BATCH * RIR_LENGTH + b] =
            __fadd_rn((float)PAD, __fmul_rn(__fsqrt_rn(ssq), FSR));
    }
    __syncthreads();

    const float d0 = sGeo[0], d1 = sGeo[1], d2 = sGeo[2];
    const float m0 = sGeo[3], m1 = sGeo[4], m2 = sGeo[5];
    const float s0 = sGeo[6], s1 = sGeo[7], s2v = sGeo[8];

    // ---- phase A: raw 31^3 grid scan, histogram + ballot compaction ----
    for (int it = 0; it < GITER; it++) {
        int idx = it * TPB + tid;
        bool live = false;
        float delay = 0.f, amp = 0.f;
        if (idx < GRID_TOT) {
            int iz  = idx / 961;
            int rem = idx - iz * 961;
            int iy  = rem / 31;
            int ix  = rem - iy * 31;
            ix -= MAXO; iy -= MAXO; iz -= MAXO;
            int axy = abs(ix) + abs(iy);
            if (axy + abs(iz) <= MAXO) {
                float img0 = (ix & 1) ? __fsub_rn(__fmul_rn(d0, (float)(ix + 1)), s0)
                                      : __fadd_rn(__fmul_rn(d0, (float)ix), s0);
                float img1 = (iy & 1) ? __fsub_rn(__fmul_rn(d1, (float)(iy + 1)), s1)
                                      : __fadd_rn(__fmul_rn(d1, (float)iy), s1);
                float img2 = (iz & 1) ? __fsub_rn(__fmul_rn(d2, (float)(iz + 1)), s2v)
                                      : __fadd_rn(__fmul_rn(d2, (float)iz), s2v);
                float e0 = __fsub_rn(img0, m0);
                float e1 = __fsub_rn(img1, m1);
                float e2 = __fsub_rn(img2, m2);
                float ssq = __fadd_rn(__fadd_rn(__fmul_rn(e0, e0), __fmul_rn(e1, e1)),
                                      __fmul_rn(e2, e2));
                float dist = __fsqrt_rn(ssq);
                delay = __fmul_rn(dist, FSR);
                float dif = ceilf(delay);
                int   di  = (int)dif;
                if (di <= DIMAX) {
                    live = true;
                    int elo2 = (iz >= 0) ? (iz >> 1)       : ((-iz + 1) >> 1);
                    int ehi2 = (iz >= 0) ? ((iz + 1) >> 1) : ((-iz) >> 1);
                    float att = sPW[axy] * sPL[elo2] * sPH[ehi2];
                    amp = __fdiv_rn(att, dist);
                    if (__fsub_rn(dif, delay) != 0.0f)
                        atomicAdd(&hist[di >> BSH], 1);
                }
            }
        }
        unsigned msk = __ballot_sync(0xffffffffu, live);
        if (msk) {
            int cnt = __popc(msk);
            int ldr = __ffs(msk) - 1;
            int bp  = 0;
            if (lane == ldr) bp = atomicAdd(&s_icnt, cnt);
            bp = __shfl_sync(0xffffffffu, bp, ldr);
            if (live) {
                int rk = __popc(msk & ((1u << lane) - 1u));
                sCache[bp + rk] = make_float2(delay, amp);
            }
        }
    }
    __syncthreads();

    // ---- two-level prefix scan over NBUCK buckets (32 segments of 32) ----
    if (tid < 32) {
        int s = 0;
        int q0 = tid * 32;
        #pragma unroll
        for (int q = 0; q < 32; q++) {
            int k = q0 + q;
            if (k < NBUCK) s += hist[k];
        }
        int x = s;
        #pragma unroll
        for (int d = 1; d < 32; d <<= 1) {
            int v = __shfl_up_sync(0xffffffffu, x, d);
            if (tid >= d) x += v;
        }
        segbase[tid] = x - s;
        if (tid == 31) segbase[32] = x;
    }
    __syncthreads();
    for (int k = tid; k < NBUCK; k += TPB) {
        int s = segbase[k >> 5];
        for (int q = k & ~31; q < k; q++) s += hist[q];
        base[k] = s;
        cur[k]  = s;
        g_baseG[b][k] = s;
    }
    if (tid == 0) { base[NBUCK] = segbase[32]; g_baseG[b][NBUCK] = segbase[32]; }
    __syncthreads();

    // sentinel pad (disjoint from entry slots, can fill now)
    {
        int ntot = base[NBUCK];
        float4* slab = g_ent + b * ESTRIDE;
        for (int k = tid; k < EPAD; k += TPB)
            slab[ntot + k] = make_float4(1e9f, 0.f, 0.f, 0.f);
    }

    // ---- phase B: finalize entries -> global slab ----
    int n_img = s_icnt;
    float4* slab = g_ent + b * ESTRIDE;
    for (int c = tid; c < n_img; c += TPB) {
        float2 E = sCache[c];
        float delay = E.x, amp = E.y;
        float dif = ceilf(delay);
        int   di  = (int)dif;
        float frac = __fsub_rn(dif, delay);
        if (frac == 0.0f) {                    // pure spike: sinc peak only
            if (di < RIR_LENGTH) {
                int sp = atomicAdd(&s_nsp, 1);
                if (sp < SPMAX) { g_spkiG[b][sp] = di; g_spkaG[b][sp] = amp; }
            }
            continue;
        }
        float a2 = 0.5f * INV_PI * amp * sinpif(frac);
        if (di & 1) a2 = -a2;                  // (-1)^di
        int dm = di % 80;
        float cD, sD;
        sincospif(((float)dm - frac) * 0.025f, &sD, &cD);
        int slot = atomicAdd(&cur[di >> BSH], 1);
        slab[slot] = make_float4(delay, a2, a2 * cD, a2 * sD);
        if (di < PAD) {                        // near-field: JAX wrap duplicate
            int w = atomicAdd(&s_nwr, 1);
            if (w < WMAX) {
                int dm2 = (dm + 48) % 80;      // (di + 3968) % 80
                float cW, sW;
                sincospif(((float)dm2 - frac) * 0.025f, &sW, &cW);
                g_wrapG[b][2 * w + 0] = make_float4((float)(di + RIR_LENGTH), frac, a2, 0.f);
                g_wrapG[b][2 * w + 1] = make_float4(cW, sW, 0.f, 0.f);
            }
        }
    }
    __syncthreads();
    if (tid == 0) {
        g_nspG[b] = min(s_nsp, SPMAX);
        g_nwrG[b] = min(s_nwr, WMAX);
    }
}

// ---------------------------------------------------------------------------
// Gather: one bin per thread, 992 bins per block, 2 blocks/SM.
#define GBINS 992
__global__ __launch_bounds__(TPB, 2) void k_gather(float* __restrict__ out) {
    const int b   = blockIdx.y;
    const int tid = threadIdx.x;
    const int j   = blockIdx.x * GBINS + tid;
    const bool act = (tid < GBINS);            // warp-uniform (992 % 32 == 0)

    const float jf = (float)j;
    const int jm = j % 80;
    float cj, sj;
    sincospif((float)jm * 0.025f, &sj, &cj);
    const float onej = (jm & 1) ? -1.f : 1.f;

    int g8  = blockIdx.x * GBINS + (tid & ~7); // 8-lane group base bin
    int lob = (g8 - 39) >> BSH; lob = max(lob, 0);
    int hib = (g8 + 47) >> BSH; hib = min(hib, NBUCK - 1);
    const int* bb = g_baseG[b];
    int elo = bb[lob];
    int cnt = act ? (bb[hib + 1] - elo) : 0;
    int mc  = __reduce_max_sync(0xffffffffu, cnt);

    const float4* __restrict__ p = g_ent + b * ESTRIDE + elo;
    float a0 = 0.f, a1 = 0.f;
    int it = 0;
    for (; it + 4 <= mc; it += 4) {
        float4 E0 = p[it], E1 = p[it + 1], E2 = p[it + 2], E3 = p[it + 3];
        {
            float x = jf - E0.x;
            float t = fmaf(cj, E0.z, E0.y);
            t = fmaf(sj, E0.w, t);
            t = (fabsf(x) < 40.f) ? t : 0.f;
            a0 = fmaf(t, __fdividef(1.f, x), a0);
        }
        {
            float x = jf - E1.x;
            float t = fmaf(cj, E1.z, E1.y);
            t = fmaf(sj, E1.w, t);
            t = (fabsf(x) < 40.f) ? t : 0.f;
            a1 = fmaf(t, __fdividef(1.f, x), a1);
        }
        {
            float x = jf - E2.x;
            float t = fmaf(cj, E2.z, E2.y);
            t = fmaf(sj, E2.w, t);
            t = (fabsf(x) < 40.f) ? t : 0.f;
            a0 = fmaf(t, __fdividef(1.f, x), a0);
        }
        {
            float x = jf - E3.x;
            float t = fmaf(cj, E3.z, E3.y);
            t = fmaf(sj, E3.w, t);
            t = (fabsf(x) < 40.f) ? t : 0.f;
            a1 = fmaf(t, __fdividef(1.f, x), a1);
        }
    }
    for (; it < mc; it++) {
        float4 E0 = p[it];
        float x = jf - E0.x;
        float t = fmaf(cj, E0.z, E0.y);
        t = fmaf(sj, E0.w, t);
        t = (fabsf(x) < 40.f) ? t : 0.f;
        a0 = fmaf(t, __fdividef(1.f, x), a0);
    }
    float acc = a0 + a1;

    // wrapped near-field taps land only in bins [3928, 3967]
    if (act && j >= RIR_LENGTH - PAD) {
        int nwr = g_nwrG[b];
        for (int w = 0; w < nwr; w++) {
            float4 A = g_wrapG[b][2 * w], B = g_wrapG[b][2 * w + 1];
            float x = (jf - A.x) + A.y;        // exact: int diff + frac
            float t = fmaf(cj, B.x, 1.f);
            t = fmaf(sj, B.y, t);
            t = (fabsf(x) < 40.f) ? t : 0.f;
            acc = fmaf(A.z * t, __fdividef(1.f, x), acc);
        }
    }
    acc *= onej;                               // deferred (-1)^j
    // spikes (rare)
    int nsp = g_nspG[b];
    for (int sp = 0; sp < nsp; sp++)
        if (g_spkiG[b][sp] == j) acc += g_spkaG[b][sp];

    if (act) out[b * RIR_LENGTH + j] = acc;
}

// ---------------------------------------------------------------------------
extern "C" void kernel_launch(void* const* d_in, const int* in_sizes, int n_in,
                              void* d_out, int out_size) {
    const float* inp = (const float*)d_in[0];
    float* out = (float*)d_out;

    const int prepsm = MAXE * (int)sizeof(float2);   // 39,936
    cudaFuncSetAttribute(k_prep, cudaFuncAttributeMaxDynamicSharedMemorySize, prepsm);
    k_prep<<<BATCH, TPB, prepsm>>>(inp, out);
    k_gather<<<dim3(RIR_LENGTH / GBINS, BATCH), TPB>>>(out);
}

// round 12
// speedup vs baseline: 1.2757x; 1.2757x over previous
#include <cuda_runtime.h>
#include <math.h>

#define RIR_LENGTH 3968
#define PAD        40
#define BATCH      128
#define MAXO       15
#define GRID_TOT   29791
#define NIMG       4991          // |x|+|y|+|z| <= 15 lattice points
#define FSR        46.64723032f  // fp32(16000/343)
#define INV_PI     0.3183098862f

#define DIMAX      4007          // di <= 4007 <=> lowest tap bin <= 3967
#define BSH        2             // bucket = 4 delay-bins
#define NBUCK      1002          // ceil(4008/4)
#define MAXE       4992
#define EPAD       512           // sentinel pad (covers warp-max overrun)
#define WMAX       64
#define SPMAX      32
#define TPB        1024
#define AITER      ((NIMG + TPB - 1) / TPB)   // 5

__device__ int g_xyz[NIMG + 32];

// closed-form prefix of octahedral layer sizes: P(m) = sum_{r=0}^{m} (2r^2+2r+1)
__device__ __forceinline__ int octP(int m) {
    return (m < 0) ? 0 : (m + 1) * (2 * m * m + 4 * m + 3) / 3;
}

// Deterministic, atomic-free compaction: lex-order rank of (ix,iy,iz).
__global__ void k_build_xyz() {
    int idx = blockIdx.x * blockDim.x + threadIdx.x;
    if (idx >= GRID_TOT) return;
    int iz  = idx / 961;
    int rem = idx - iz * 961;
    int iy  = rem / 31;
    int ix  = rem - iy * 31;
    ix -= MAXO; iy -= MAXO; iz -= MAXO;
    int ax = abs(ix), ay = abs(iy), az = abs(iz);
    if (ax + ay + az > MAXO) return;
    int Cx = (ix <= 0) ? octP(ix + 14) : 2736 + 2255 - octP(15 - ix);
    int r  = MAXO - ax;
    int Cy = (iy <= 0) ? (iy + r) * (iy + r)
                       : (r + 1) * (r + 1) + (iy - 1) * (2 * r - iy + 1);
    int slot = Cx + Cy + iz + (r - ay);
    g_xyz[slot] = (ix + 16) | ((iy + 16) << 8) | ((iz + 16) << 16);
}

// evaluate one entry against one bin
#define EVAL(E, JF, CJ, SJ, ACC) do {                    \
    float x_ = (JF) - (E).x;                             \
    float t_ = fmaf((CJ), (E).z, (E).y);                 \
    t_ = fmaf((SJ), (E).w, t_);                          \
    t_ = (fabsf(x_) < 40.f) ? t_ : 0.f;                  \
    (ACC) = fmaf(t_, __fdividef(1.f, x_), (ACC));        \
} while (0)

// ---------------------------------------------------------------------------
__global__ __launch_bounds__(TPB) void k_all(const float* __restrict__ inp,
                                             float* __restrict__ out) {
    extern __shared__ __align__(16) char dynsm[];
    float4* sEnt   = (float4*)dynsm;                                     // [MAXE+EPAD]
    float2* sCache = (float2*)(dynsm + (MAXE + EPAD) * sizeof(float4));  // [MAXE]

    __shared__ float  sPW[16], sPL[9], sPH[9], sGeo[9];
    __shared__ float2 sCS[80];
    __shared__ int    hist[NBUCK], base[NBUCK + 1], cur[NBUCK];
    __shared__ int    segbase[33];
    __shared__ int    s_nsp, s_nwr;
    __shared__ int    s_spk_i[SPMAX];
    __shared__ float  s_spk_a[SPMAX];
    __shared__ float4 s_wrap[WMAX * 2];

    const int b    = blockIdx.x;
    const int tid  = threadIdx.x;
    const int warp = tid >> 5;
    const int lane = tid & 31;

    for (int k = tid; k < NBUCK; k += TPB) hist[k] = 0;
    if (tid < 80) {
        float c, s;
        sincospif((float)tid * 0.025f, &s, &c);
        sCS[tid] = make_float2(c, s);
    }
    if (tid == 0) {
        s_nsp = 0; s_nwr = 0;
        const float* r = inp + b * 12;
        float rx = r[0], ry = r[1], rz = r[2];
        sGeo[0] = rx;                  sGeo[1] = ry;                  sGeo[2] = rz;
        sGeo[3] = __fmul_rn(r[3], rx); sGeo[4] = __fmul_rn(r[4], ry); sGeo[5] = __fmul_rn(r[5], rz);
        sGeo[6] = __fmul_rn(r[6], rx); sGeo[7] = __fmul_rn(r[7], ry); sGeo[8] = __fmul_rn(r[8], rz);
        float aw  = __fadd_rn(__fmul_rn(r[9],  0.84f), 0.01f);
        float a4  = __fadd_rn(__fmul_rn(r[10], 0.84f), 0.01f);
        float a5  = __fadd_rn(__fmul_rn(r[11], 0.84f), 0.01f);
        double trw = sqrt(1.0 - (double)aw);
        double tr4 = sqrt(1.0 - (double)a4);
        double tr5 = sqrt(1.0 - (double)a5);
        double p = 1.0;
        for (int e = 0; e < 16; e++) { sPW[e] = (float)p; p *= trw; }
        p = 1.0;
        for (int e = 0; e < 9;  e++) { sPL[e] = (float)p; p *= tr4; }
        p = 1.0;
        for (int e = 0; e < 9;  e++) { sPH[e] = (float)p; p *= tr5; }
        // toa
        float dx = __fsub_rn(__fmul_rn(r[3], rx), __fmul_rn(r[6], rx));
        float dy = __fsub_rn(__fmul_rn(r[4], ry), __fmul_rn(r[7], ry));
        float dz = __fsub_rn(__fmul_rn(r[5], rz), __fmul_rn(r[8], rz));
        float ssq = __fadd_rn(__fadd_rn(__fmul_rn(dx, dx), __fmul_rn(dy, dy)),
                              __fmul_rn(dz, dz));
        out[BATCH * RIR_LENGTH + b] =
            __fadd_rn((float)PAD, __fmul_rn(__fsqrt_rn(ssq), FSR));
    }
    __syncthreads();

    const float d0 = sGeo[0], d1 = sGeo[1], d2 = sGeo[2];
    const float m0 = sGeo[3], m1 = sGeo[4], m2 = sGeo[5];
    const float s0 = sGeo[6], s1 = sGeo[7], s2v = sGeo[8];

    // ---- phase A: per-image delay/amp + histogram ----
    #pragma unroll
    for (int it = 0; it < AITER; it++) {
        int i = it * TPB + tid;
        if (i >= NIMG) break;
        int pk = g_xyz[i];
        int ix = (pk & 255) - 16;
        int iy = ((pk >> 8) & 255) - 16;
        int iz = (pk >> 16) - 16;
        float img0 = (ix & 1) ? __fsub_rn(__fmul_rn(d0, (float)(ix + 1)), s0)
                              : __fadd_rn(__fmul_rn(d0, (float)ix), s0);
        float img1 = (iy & 1) ? __fsub_rn(__fmul_rn(d1, (float)(iy + 1)), s1)
                              : __fadd_rn(__fmul_rn(d1, (float)iy), s1);
        float img2 = (iz & 1) ? __fsub_rn(__fmul_rn(d2, (float)(iz + 1)), s2v)
                              : __fadd_rn(__fmul_rn(d2, (float)iz), s2v);
        float e0 = __fsub_rn(img0, m0);
        float e1 = __fsub_rn(img1, m1);
        float e2 = __fsub_rn(img2, m2);
        float ssq = __fadd_rn(__fadd_rn(__fmul_rn(e0, e0), __fmul_rn(e1, e1)),
                              __fmul_rn(e2, e2));
        float dist  = __fsqrt_rn(ssq);
        float delay = __fmul_rn(dist, FSR);
        float dif   = ceilf(delay);
        int   di    = (int)dif;
        float amp   = -1.0f;
        if (di <= DIMAX) {
            int axy  = abs(ix) + abs(iy);
            int elo2 = (iz >= 0) ? (iz >> 1)       : ((-iz + 1) >> 1);
            int ehi2 = (iz >= 0) ? ((iz + 1) >> 1) : ((-iz) >> 1);
            float att = sPW[axy] * sPL[elo2] * sPH[ehi2];
            amp = __fdiv_rn(att, dist);
            if (__fsub_rn(dif, delay) != 0.0f)
                atomicAdd(&hist[di >> BSH], 1);
        }
        sCache[i] = make_float2(delay, amp);
    }
    __syncthreads();

    // ---- two-level prefix scan over NBUCK buckets (32 segments of 32) ----
    if (tid < 32) {
        int s = 0;
        int q0 = tid * 32;
        #pragma unroll
        for (int q = 0; q < 32; q++) {
            int k = q0 + q;
            if (k < NBUCK) s += hist[k];
        }
        int x = s;
        #pragma unroll
        for (int d = 1; d < 32; d <<= 1) {
            int v = __shfl_up_sync(0xffffffffu, x, d);
            if (tid >= d) x += v;
        }
        segbase[tid] = x - s;
        if (tid == 31) segbase[32] = x;
    }
    __syncthreads();
    for (int k = tid; k < NBUCK; k += TPB) {
        int s = segbase[k >> 5];
        for (int q = k & ~31; q < k; q++) s += hist[q];
        base[k] = s;
        cur[k]  = s;
    }
    if (tid == 0) base[NBUCK] = segbase[32];
    __syncthreads();

    // ---- phase B: finalize entries (pre-scaled by a2) ----
    #pragma unroll
    for (int it = 0; it < AITER; it++) {
        int c = it * TPB + tid;
        if (c >= NIMG) break;
        float2 E = sCache[c];
        float delay = E.x, amp = E.y;
        if (amp < 0.0f) continue;              // culled (di > DIMAX)
        float dif = ceilf(delay);
        int   di  = (int)dif;
        float frac = __fsub_rn(dif, delay);
        if (frac == 0.0f) {                    // pure spike: sinc peak only
            if (di < RIR_LENGTH) {
                int sp = atomicAdd(&s_nsp, 1);
                if (sp < SPMAX) { s_spk_i[sp] = di; s_spk_a[sp] = amp; }
            }
            continue;
        }
        float a2 = 0.5f * INV_PI * amp * sinpif(frac);
        if (di & 1) a2 = -a2;                  // (-1)^di
        int dm = di % 80;
        float cD, sD;
        sincospif(((float)dm - frac) * 0.025f, &sD, &cD);
        int slot = atomicAdd(&cur[di >> BSH], 1);
        sEnt[slot] = make_float4(delay, a2, a2 * cD, a2 * sD);
        if (di < PAD) {                        // near-field: JAX wrap duplicate
            int w = atomicAdd(&s_nwr, 1);
            if (w < WMAX) {
                int dm2 = (dm + 48) % 80;      // (di + 3968) % 80
                float cW, sW;
                sincospif(((float)dm2 - frac) * 0.025f, &sW, &cW);
                s_wrap[2 * w + 0] = make_float4((float)(di + RIR_LENGTH), frac, a2, 0.f);
                s_wrap[2 * w + 1] = make_float4(cW, sW, 0.f, 0.f);
            }
        }
    }
    __syncthreads();

    // sentinel pad: overruns read delay=1e9, coeffs=0 -> contribute exactly 0
    {
        int ntot = base[NBUCK];
        for (int k = tid; k < EPAD; k += TPB)
            sEnt[ntot + k] = make_float4(1e9f, 0.f, 0.f, 0.f);
    }
    __syncthreads();

    // ---- phase D: paired-bin gather, 2 independent chains per thread ----
    int nsp = min(s_nsp, SPMAX);
    int nwr = min(s_nwr, WMAX);
    float* orir = out + b * RIR_LENGTH;

    #pragma unroll
    for (int half = 0; half < 2; half++) {
        int wbase = half * 2048 + warp * 64;   // warp covers 64 consecutive bins
        int j0 = wbase + lane;
        int j1 = j0 + 32;
        bool act0 = (j0 < RIR_LENGTH);         // warp-uniform
        bool act1 = (j1 < RIR_LENGTH);

        float jf0 = (float)j0, jf1 = (float)j1;
        int jm0 = j0 % 80, jm1 = j1 % 80;
        float2 cs0 = sCS[jm0], cs1 = sCS[jm1];
        float cj0 = cs0.x, sj0 = cs0.y, cj1 = cs1.x, sj1 = cs1.y;
        float onej0 = (jm0 & 1) ? -1.f : 1.f;
        float onej1 = (jm1 & 1) ? -1.f : 1.f;

        int g0 = j0 & ~7, g1 = j1 & ~7;        // 8-lane group bases
        int lob0 = max((g0 - 39) >> BSH, 0);
        int hib0 = min((g0 + 47) >> BSH, NBUCK - 1);
        int lob1 = max((g1 - 39) >> BSH, 0);
        int hib1 = min((g1 + 47) >> BSH, NBUCK - 1);
        int elo0 = base[lob0];
        int elo1 = base[lob1];
        int cnt0 = act0 ? (base[hib0 + 1] - elo0) : 0;
        int cnt1 = act1 ? (base[hib1 + 1] - elo1) : 0;
        int mc = __reduce_max_sync(0xffffffffu, max(cnt0, cnt1));

        const float4* p0 = sEnt + elo0;
        const float4* p1 = sEnt + elo1;
        float a00 = 0.f, a01 = 0.f, a10 = 0.f, a11 = 0.f;
        int it = 0;
        for (; it + 2 <= mc; it += 2) {
            float4 A0 = p0[it], A1 = p0[it + 1];
            float4 B0 = p1[it], B1 = p1[it + 1];
            EVAL(A0, jf0, cj0, sj0, a00);
            EVAL(B0, jf1, cj1, sj1, a10);
            EVAL(A1, jf0, cj0, sj0, a01);
            EVAL(B1, jf1, cj1, sj1, a11);
        }
        if (it < mc) {
            float4 A0 = p0[it];
            float4 B0 = p1[it];
            EVAL(A0, jf0, cj0, sj0, a00);
            EVAL(B0, jf1, cj1, sj1, a10);
        }
        float acc0 = a00 + a01;
        float acc1 = a10 + a11;

        // wrapped near-field taps land only in bins [3928, 3967]
        if (act0 && j0 >= RIR_LENGTH - PAD) {
            for (int w = 0; w < nwr; w++) {
                float4 A = s_wrap[2 * w], B = s_wrap[2 * w + 1];
                float x = (jf0 - A.x) + A.y;
                float t = fmaf(cj0, B.x, 1.f);
                t = fmaf(sj0, B.y, t);
                t = (fabsf(x) < 40.f) ? t : 0.f;
                acc0 = fmaf(A.z * t, __fdividef(1.f, x), acc0);
            }
        }
        if (act1 && j1 >= RIR_LENGTH - PAD) {
            for (int w = 0; w < nwr; w++) {
                float4 A = s_wrap[2 * w], B = s_wrap[2 * w + 1];
                float x = (jf1 - A.x) + A.y;
                float t = fmaf(cj1, B.x, 1.f);
                t = fmaf(sj1, B.y, t);
                t = (fabsf(x) < 40.f) ? t : 0.f;
                acc1 = fmaf(A.z * t, __fdividef(1.f, x), acc1);
            }
        }
        acc0 *= onej0;                         // deferred (-1)^j
        acc1 *= onej1;
        for (int sp = 0; sp < nsp; sp++) {     // spikes (rare)
            if (s_spk_i[sp] == j0) acc0 += s_spk_a[sp];
            if (s_spk_i[sp] == j1) acc1 += s_spk_a[sp];
        }

        if (act0) orir[j0] = acc0;
        if (act1) orir[j1] = acc1;
    }
}

// ---------------------------------------------------------------------------
extern "C" void kernel_launch(void* const* d_in, const int* in_sizes, int n_in,
                              void* d_out, int out_size) {
    const float* inp = (const float*)d_in[0];
    float* out = (float*)d_out;

    const int dynbytes = (MAXE + EPAD) * (int)sizeof(float4)
                       + MAXE * (int)sizeof(float2);          // 128,000
    cudaFuncSetAttribute(k_all, cudaFuncAttributeMaxDynamicSharedMemorySize, dynbytes);
    k_build_xyz<<<(GRID_TOT + 255) / 256, 256>>>();
    k_all<<<BATCH, TPB, dynbytes>>>(inp, out);
}

// round 13
// speedup vs baseline: 1.9261x; 1.5099x over previous
#include <cuda_runtime.h>
#include <math.h>

#define RIR_LENGTH 3968
#define PAD        40
#define BATCH      128
#define MAXO       15
#define GRID_TOT   29791
#define NIMG       4991          // |x|+|y|+|z| <= 15 lattice points
#define FSR        46.64723032f  // fp32(16000/343)
#define INV_PI     0.3183098862f

#define DIMAX      4007          // di <= 4007 <=> lowest tap bin <= 3967
#define BSH        2             // bucket = 4 delay-bins
#define NBUCK      1002          // ceil(4008/4)
#define MAXE       4992
#define EPAD       512           // sentinel pad (covers worst-case group scan)
#define WMAX       64
#define SPMAX      32
#define TPB        1024
#define AITER      ((NIMG + TPB - 1) / TPB)   // 5

__device__ int g_xyz[NIMG + 32];

// closed-form prefix of octahedral layer sizes: P(m) = sum_{r=0}^{m} (2r^2+2r+1)
__device__ __forceinline__ int octP(int m) {
    return (m < 0) ? 0 : (m + 1) * (2 * m * m + 4 * m + 3) / 3;
}

// Deterministic, atomic-free compaction: lex-order rank of (ix,iy,iz).
__global__ void k_build_xyz() {
    int idx = blockIdx.x * blockDim.x + threadIdx.x;
    if (idx >= GRID_TOT) return;
    int iz  = idx / 961;
    int rem = idx - iz * 961;
    int iy  = rem / 31;
    int ix  = rem - iy * 31;
    ix -= MAXO; iy -= MAXO; iz -= MAXO;
    int ax = abs(ix), ay = abs(iy), az = abs(iz);
    if (ax + ay + az > MAXO) return;
    int Cx = (ix <= 0) ? octP(ix + 14) : 2736 + 2255 - octP(15 - ix);
    int r  = MAXO - ax;
    int Cy = (iy <= 0) ? (iy + r) * (iy + r)
                       : (r + 1) * (r + 1) + (iy - 1) * (2 * r - iy + 1);
    int slot = Cx + Cy + iz + (r - ay);
    g_xyz[slot] = (ix + 16) | ((iy + 16) << 8) | ((iz + 16) << 16);
}

// ---------------------------------------------------------------------------
__global__ __launch_bounds__(TPB) void k_all(const float* __restrict__ inp,
                                             float* __restrict__ out) {
    extern __shared__ __align__(16) char dynsm[];
    float4* sEnt   = (float4*)dynsm;                                     // [MAXE+EPAD]
    float2* sCache = (float2*)(dynsm + (MAXE + EPAD) * sizeof(float4));  // [MAXE]

    __shared__ float  sPW[16], sPL[9], sPH[9], sGeo[9];
    __shared__ float2 sCS[80];
    __shared__ int    hist[NBUCK], base[NBUCK + 1], cur[NBUCK];
    __shared__ int    segbase[33];
    __shared__ int    s_nsp, s_nwr;
    __shared__ int    s_spk_i[SPMAX];
    __shared__ float  s_spk_a[SPMAX];
    __shared__ float4 s_wrap[WMAX * 2];

    const int b   = blockIdx.x;
    const int tid = threadIdx.x;

    for (int k = tid; k < NBUCK; k += TPB) hist[k] = 0;
    if (tid < 80) {
        float c, s;
        sincospif((float)tid * 0.025f, &s, &c);
        sCS[tid] = make_float2(c, s);
    }
    if (tid == 0) {
        s_nsp = 0; s_nwr = 0;
        const float* r = inp + b * 12;
        float rx = r[0], ry = r[1], rz = r[2];
        sGeo[0] = rx;                  sGeo[1] = ry;                  sGeo[2] = rz;
        sGeo[3] = __fmul_rn(r[3], rx); sGeo[4] = __fmul_rn(r[4], ry); sGeo[5] = __fmul_rn(r[5], rz);
        sGeo[6] = __fmul_rn(r[6], rx); sGeo[7] = __fmul_rn(r[7], ry); sGeo[8] = __fmul_rn(r[8], rz);
        float aw  = __fadd_rn(__fmul_rn(r[9],  0.84f), 0.01f);
        float a4  = __fadd_rn(__fmul_rn(r[10], 0.84f), 0.01f);
        float a5  = __fadd_rn(__fmul_rn(r[11], 0.84f), 0.01f);
        double trw = sqrt(1.0 - (double)aw);
        double tr4 = sqrt(1.0 - (double)a4);
        double tr5 = sqrt(1.0 - (double)a5);
        double p = 1.0;
        for (int e = 0; e < 16; e++) { sPW[e] = (float)p; p *= trw; }
        p = 1.0;
        for (int e = 0; e < 9;  e++) { sPL[e] = (float)p; p *= tr4; }
        p = 1.0;
        for (int e = 0; e < 9;  e++) { sPH[e] = (float)p; p *= tr5; }
        // toa
        float dx = __fsub_rn(__fmul_rn(r[3], rx), __fmul_rn(r[6], rx));
        float dy = __fsub_rn(__fmul_rn(r[4], ry), __fmul_rn(r[7], ry));
        float dz = __fsub_rn(__fmul_rn(r[5], rz), __fmul_rn(r[8], rz));
        float ssq = __fadd_rn(__fadd_rn(__fmul_rn(dx, dx), __fmul_rn(dy, dy)),
                              __fmul_rn(dz, dz));
        out[BATCH * RIR_LENGTH + b] =
            __fadd_rn((float)PAD, __fmul_rn(__fsqrt_rn(ssq), FSR));
    }
    __syncthreads();

    const float d0 = sGeo[0], d1 = sGeo[1], d2 = sGeo[2];
    const float m0 = sGeo[3], m1 = sGeo[4], m2 = sGeo[5];
    const float s0 = sGeo[6], s1 = sGeo[7], s2v = sGeo[8];

    // ---- phase A: per-image delay/amp + histogram ----
    #pragma unroll
    for (int it = 0; it < AITER; it++) {
        int i = it * TPB + tid;
        if (i >= NIMG) break;
        int pk = g_xyz[i];
        int ix = (pk & 255) - 16;
        int iy = ((pk >> 8) & 255) - 16;
        int iz = (pk >> 16) - 16;
        float img0 = (ix & 1) ? __fsub_rn(__fmul_rn(d0, (float)(ix + 1)), s0)
                              : __fadd_rn(__fmul_rn(d0, (float)ix), s0);
        float img1 = (iy & 1) ? __fsub_rn(__fmul_rn(d1, (float)(iy + 1)), s1)
                              : __fadd_rn(__fmul_rn(d1, (float)iy), s1);
        float img2 = (iz & 1) ? __fsub_rn(__fmul_rn(d2, (float)(iz + 1)), s2v)
                              : __fadd_rn(__fmul_rn(d2, (float)iz), s2v);
        float e0 = __fsub_rn(img0, m0);
        float e1 = __fsub_rn(img1, m1);
        float e2 = __fsub_rn(img2, m2);
        float ssq = __fadd_rn(__fadd_rn(__fmul_rn(e0, e0), __fmul_rn(e1, e1)),
                              __fmul_rn(e2, e2));
        float dist  = __fsqrt_rn(ssq);
        float delay = __fmul_rn(dist, FSR);
        float dif   = ceilf(delay);
        int   di    = (int)dif;
        float amp   = -1.0f;
        if (di <= DIMAX) {
            int axy  = abs(ix) + abs(iy);
            int elo2 = (iz >= 0) ? (iz >> 1)       : ((-iz + 1) >> 1);
            int ehi2 = (iz >= 0) ? ((iz + 1) >> 1) : ((-iz) >> 1);
            float att = sPW[axy] * sPL[elo2] * sPH[ehi2];
            amp = __fdiv_rn(att, dist);
            if (__fsub_rn(dif, delay) != 0.0f)
                atomicAdd(&hist[di >> BSH], 1);
        }
        sCache[i] = make_float2(delay, amp);
    }
    __syncthreads();

    // ---- two-level prefix scan over NBUCK buckets (32 segments of 32) ----
    if (tid < 32) {
        int s = 0;
        int q0 = tid * 32;
        #pragma unroll
        for (int q = 0; q < 32; q++) {
            int k = q0 + q;
            if (k < NBUCK) s += hist[k];
        }
        int x = s;
        #pragma unroll
        for (int d = 1; d < 32; d <<= 1) {
            int v = __shfl_up_sync(0xffffffffu, x, d);
            if (tid >= d) x += v;
        }
        segbase[tid] = x - s;
        if (tid == 31) segbase[32] = x;
    }
    __syncthreads();
    for (int k = tid; k < NBUCK; k += TPB) {
        int s = segbase[k >> 5];
        for (int q = k & ~31; q < k; q++) s += hist[q];
        base[k] = s;
        cur[k]  = s;
    }
    if (tid == 0) base[NBUCK] = segbase[32];
    __syncthreads();

    // ---- phase B: finalize entries (pre-scaled by a2) ----
    #pragma unroll
    for (int it = 0; it < AITER; it++) {
        int c = it * TPB + tid;
        if (c >= NIMG) break;
        float2 E = sCache[c];
        float delay = E.x, amp = E.y;
        if (amp < 0.0f) continue;              // culled (di > DIMAX)
        float dif = ceilf(delay);
        int   di  = (int)dif;
        float frac = __fsub_rn(dif, delay);
        if (frac == 0.0f) {                    // pure spike: sinc peak only
            if (di < RIR_LENGTH) {
                int sp = atomicAdd(&s_nsp, 1);
                if (sp < SPMAX) { s_spk_i[sp] = di; s_spk_a[sp] = amp; }
            }
            continue;
        }
        float a2 = 0.5f * INV_PI * amp * sinpif(frac);
        if (di & 1) a2 = -a2;                  // (-1)^di
        int dm = di % 80;
        float cD, sD;
        sincospif(((float)dm - frac) * 0.025f, &sD, &cD);
        int slot = atomicAdd(&cur[di >> BSH], 1);
        sEnt[slot] = make_float4(delay, a2, a2 * cD, a2 * sD);
        if (di < PAD) {                        // near-field: JAX wrap duplicate
            int w = atomicAdd(&s_nwr, 1);
            if (w < WMAX) {
                int dm2 = (dm + 48) % 80;      // (di + 3968) % 80
                float cW, sW;
                sincospif(((float)dm2 - frac) * 0.025f, &sW, &cW);
                s_wrap[2 * w + 0] = make_float4((float)(di + RIR_LENGTH), frac, a2, 0.f);
                s_wrap[2 * w + 1] = make_float4(cW, sW, 0.f, 0.f);
            }
        }
    }
    __syncthreads();

    // sentinel pad: overruns read delay=1e9, coeffs=0 -> contribute exactly 0
    {
        int ntot = base[NBUCK];
        for (int k = tid; k < EPAD; k += TPB)
            sEnt[ntot + k] = make_float4(1e9f, 0.f, 0.f, 0.f);
    }
    __syncthreads();

    // ---- phase D: gather, 8-lane groups, paired-reciprocal inner loop ----
    int nsp = min(s_nsp, SPMAX);
    int nwr = min(s_nwr, WMAX);
    float* orir = out + b * RIR_LENGTH;

    #pragma unroll
    for (int m = 0; m < 4; m++) {
        int j      = m * TPB + tid;
        int wstart = m * TPB + (tid & ~31);
        bool act   = (j < RIR_LENGTH);         // warp-uniform (3968 % 32 == 0)

        int g8 = m * TPB + (tid & ~7);         // group base bin (8-bin window)
        float jf = (float)j;
        int jm = j % 80;
        float2 cs = sCS[jm];
        float cj = cs.x, sj = cs.y;
        float onej = (jm & 1) ? -1.f : 1.f;

        int lob = (g8 - 39) >> BSH; if (lob < 0) lob = 0;
        int hib = (g8 + 47) >> BSH; if (hib > NBUCK - 1) hib = NBUCK - 1;
        int elo = base[lob];
        int cnt = act ? (base[hib + 1] - elo) : 0;
        int mc  = __reduce_max_sync(0xffffffffu, cnt);

        const float4* p = sEnt + elo;
        float a0 = 0.f, a1 = 0.f;
        int it = 0;
        for (; it + 4 <= mc; it += 4) {
            float4 E0 = p[it], E1 = p[it + 1], E2 = p[it + 2], E3 = p[it + 3];
            // pair (E0, E1): one reciprocal
            float x0 = jf - E0.x;
            float x1 = jf - E1.x;
            float t0 = fmaf(cj, E0.z, E0.y);
            t0 = fmaf(sj, E0.w, t0);
            t0 = (fabsf(x0) < 40.f) ? t0 : 0.f;
            float t1 = fmaf(cj, E1.z, E1.y);
            t1 = fmaf(sj, E1.w, t1);
            t1 = (fabsf(x1) < 40.f) ? t1 : 0.f;
            float r01 = __fdividef(1.f, x0 * x1);
            a0 = fmaf(fmaf(t0, x1, t1 * x0), r01, a0);
            // pair (E2, E3): one reciprocal
            float x2 = jf - E2.x;
            float x3 = jf - E3.x;
            float t2 = fmaf(cj, E2.z, E2.y);
            t2 = fmaf(sj, E2.w, t2);
            t2 = (fabsf(x2) < 40.f) ? t2 : 0.f;
            float t3 = fmaf(cj, E3.z, E3.y);
            t3 = fmaf(sj, E3.w, t3);
            t3 = (fabsf(x3) < 40.f) ? t3 : 0.f;
            float r23 = __fdividef(1.f, x2 * x3);
            a1 = fmaf(fmaf(t2, x3, t3 * x2), r23, a1);
        }
        for (; it < mc; it++) {
            float4 E0 = p[it];
            float x = jf - E0.x;
            float t = fmaf(cj, E0.z, E0.y);
            t = fmaf(sj, E0.w, t);
            t = (fabsf(x) < 40.f) ? t : 0.f;
            a0 = fmaf(t, __fdividef(1.f, x), a0);
        }
        float acc = a0 + a1;

        // wrapped near-field taps land only in bins [3928, 3967]
        if (act && wstart + 31 >= RIR_LENGTH - PAD) {
            for (int w = 0; w < nwr; w++) {
                float4 A = s_wrap[2 * w], B = s_wrap[2 * w + 1];
                float x = (jf - A.x) + A.y;    // exact: int diff + frac
                float t = fmaf(cj, B.x, 1.f);
                t = fmaf(sj, B.y, t);
                t = (fabsf(x) < 40.f) ? t : 0.f;
                acc = fmaf(A.z * t, __fdividef(1.f, x), acc);
            }
        }
        acc *= onej;                           // deferred (-1)^j
        // spikes (rare)
        for (int sp = 0; sp < nsp; sp++)
            if (s_spk_i[sp] == j) acc += s_spk_a[sp];

        if (act) orir[j] = acc;
    }
}

// ---------------------------------------------------------------------------
extern "C" void kernel_launch(void* const* d_in, const int* in_sizes, int n_in,
                              void* d_out, int out_size) {
    const float* inp = (const float*)d_in[0];
    float* out = (float*)d_out;

    const int dynbytes = (MAXE + EPAD) * (int)sizeof(float4)
                       + MAXE * (int)sizeof(float2);          // 128,000
    cudaFuncSetAttribute(k_all, cudaFuncAttributeMaxDynamicSharedMemorySize, dynbytes);
    k_build_xyz<<<(GRID_TOT + 255) / 256, 256>>>();
    k_all<<<BATCH, TPB, dynbytes>>>(inp, out);
}

// round 14
// speedup vs baseline: 2.0332x; 1.0556x over previous
#include <cuda_runtime.h>
#include <math.h>

#define RIR_LENGTH 3968
#define PAD        40
#define BATCH      128
#define MAXO       15
#define GRID_TOT   29791
#define NIMG       4991          // |x|+|y|+|z| <= 15 lattice points
#define FSR        46.64723032f  // fp32(16000/343)
#define INV_PI     0.3183098862f

#define DIMAX      4007          // di <= 4007 <=> lowest tap bin <= 3967
#define BSH        2             // bucket = 4 delay-bins
#define NBUCK      1002          // ceil(4008/4)
#define MAXE       4992
#define EPAD       512           // sentinel pad (covers warp-max overrun + prefetch)
#define WMAX       64
#define SPMAX      32
#define TPB        1024
#define AITER      ((NIMG + TPB - 1) / TPB)   // 5

__device__ int g_xyz[NIMG + 32];

// closed-form prefix of octahedral layer sizes: P(m) = sum_{r=0}^{m} (2r^2+2r+1)
__device__ __forceinline__ int octP(int m) {
    return (m < 0) ? 0 : (m + 1) * (2 * m * m + 4 * m + 3) / 3;
}

// Deterministic, atomic-free compaction: lex-order rank of (ix,iy,iz).
__global__ void k_build_xyz() {
    int idx = blockIdx.x * blockDim.x + threadIdx.x;
    if (idx >= GRID_TOT) return;
    int iz  = idx / 961;
    int rem = idx - iz * 961;
    int iy  = rem / 31;
    int ix  = rem - iy * 31;
    ix -= MAXO; iy -= MAXO; iz -= MAXO;
    int ax = abs(ix), ay = abs(iy), az = abs(iz);
    if (ax + ay + az > MAXO) return;
    int Cx = (ix <= 0) ? octP(ix + 14) : 2736 + 2255 - octP(15 - ix);
    int r  = MAXO - ax;
    int Cy = (iy <= 0) ? (iy + r) * (iy + r)
                       : (r + 1) * (r + 1) + (iy - 1) * (2 * r - iy + 1);
    int slot = Cx + Cy + iz + (r - ay);
    g_xyz[slot] = (ix + 16) | ((iy + 16) << 8) | ((iz + 16) << 16);
}

// ---------------------------------------------------------------------------
__global__ __launch_bounds__(TPB) void k_all(const float* __restrict__ inp,
                                             float* __restrict__ out) {
    extern __shared__ __align__(16) char dynsm[];
    float4* sEnt   = (float4*)dynsm;                                     // [MAXE+EPAD]
    float2* sCache = (float2*)(dynsm + (MAXE + EPAD) * sizeof(float4));  // [MAXE]

    __shared__ float  sPW[16], sPL[9], sPH[9], sGeo[9];
    __shared__ float2 sCS[80];
    __shared__ int    hist[NBUCK], base[NBUCK + 1], cur[NBUCK];
    __shared__ int    segbase[33];
    __shared__ int    s_nsp, s_nwr;
    __shared__ int    s_spk_i[SPMAX];
    __shared__ float  s_spk_a[SPMAX];
    __shared__ float4 s_wrap[WMAX * 2];

    const int b   = blockIdx.x;
    const int tid = threadIdx.x;

    for (int k = tid; k < NBUCK; k += TPB) hist[k] = 0;
    if (tid < 80) {
        float c, s;
        sincospif((float)tid * 0.025f, &s, &c);
        sCS[tid] = make_float2(c, s);
    }
    if (tid == 0) {
        s_nsp = 0; s_nwr = 0;
        const float* r = inp + b * 12;
        float rx = r[0], ry = r[1], rz = r[2];
        sGeo[0] = rx;                  sGeo[1] = ry;                  sGeo[2] = rz;
        sGeo[3] = __fmul_rn(r[3], rx); sGeo[4] = __fmul_rn(r[4], ry); sGeo[5] = __fmul_rn(r[5], rz);
        sGeo[6] = __fmul_rn(r[6], rx); sGeo[7] = __fmul_rn(r[7], ry); sGeo[8] = __fmul_rn(r[8], rz);
        float aw  = __fadd_rn(__fmul_rn(r[9],  0.84f), 0.01f);
        float a4  = __fadd_rn(__fmul_rn(r[10], 0.84f), 0.01f);
        float a5  = __fadd_rn(__fmul_rn(r[11], 0.84f), 0.01f);
        double trw = sqrt(1.0 - (double)aw);
        double tr4 = sqrt(1.0 - (double)a4);
        double tr5 = sqrt(1.0 - (double)a5);
        double p = 1.0;
        for (int e = 0; e < 16; e++) { sPW[e] = (float)p; p *= trw; }
        p = 1.0;
        for (int e = 0; e < 9;  e++) { sPL[e] = (float)p; p *= tr4; }
        p = 1.0;
        for (int e = 0; e < 9;  e++) { sPH[e] = (float)p; p *= tr5; }
        // toa
        float dx = __fsub_rn(__fmul_rn(r[3], rx), __fmul_rn(r[6], rx));
        float dy = __fsub_rn(__fmul_rn(r[4], ry), __fmul_rn(r[7], ry));
        float dz = __fsub_rn(__fmul_rn(r[5], rz), __fmul_rn(r[8], rz));
        float ssq = __fadd_rn(__fadd_rn(__fmul_rn(dx, dx), __fmul_rn(dy, dy)),
                              __fmul_rn(dz, dz));
        out[BATCH * RIR_LENGTH + b] =
            __fadd_rn((float)PAD, __fmul_rn(__fsqrt_rn(ssq), FSR));
    }
    __syncthreads();

    const float d0 = sGeo[0], d1 = sGeo[1], d2 = sGeo[2];
    const float m0 = sGeo[3], m1 = sGeo[4], m2 = sGeo[5];
    const float s0 = sGeo[6], s1 = sGeo[7], s2v = sGeo[8];

    // ---- phase A: per-image delay/amp + histogram ----
    #pragma unroll
    for (int it = 0; it < AITER; it++) {
        int i = it * TPB + tid;
        if (i >= NIMG) break;
        int pk = g_xyz[i];
        int ix = (pk & 255) - 16;
        int iy = ((pk >> 8) & 255) - 16;
        int iz = (pk >> 16) - 16;
        float img0 = (ix & 1) ? __fsub_rn(__fmul_rn(d0, (float)(ix + 1)), s0)
                              : __fadd_rn(__fmul_rn(d0, (float)ix), s0);
        float img1 = (iy & 1) ? __fsub_rn(__fmul_rn(d1, (float)(iy + 1)), s1)
                              : __fadd_rn(__fmul_rn(d1, (float)iy), s1);
        float img2 = (iz & 1) ? __fsub_rn(__fmul_rn(d2, (float)(iz + 1)), s2v)
                              : __fadd_rn(__fmul_rn(d2, (float)iz), s2v);
        float e0 = __fsub_rn(img0, m0);
        float e1 = __fsub_rn(img1, m1);
        float e2 = __fsub_rn(img2, m2);
        float ssq = __fadd_rn(__fadd_rn(__fmul_rn(e0, e0), __fmul_rn(e1, e1)),
                              __fmul_rn(e2, e2));
        float dist  = __fsqrt_rn(ssq);
        float delay = __fmul_rn(dist, FSR);
        float dif   = ceilf(delay);
        int   di    = (int)dif;
        float amp   = -1.0f;
        if (di <= DIMAX) {
            int axy  = abs(ix) + abs(iy);
            int elo2 = (iz >= 0) ? (iz >> 1)       : ((-iz + 1) >> 1);
            int ehi2 = (iz >= 0) ? ((iz + 1) >> 1) : ((-iz) >> 1);
            float att = sPW[axy] * sPL[elo2] * sPH[ehi2];
            amp = __fdiv_rn(att, dist);
            if (__fsub_rn(dif, delay) != 0.0f)
                atomicAdd(&hist[di >> BSH], 1);
        }
        sCache[i] = make_float2(delay, amp);
    }
    __syncthreads();

    // ---- two-level prefix scan over NBUCK buckets (32 segments of 32) ----
    if (tid < 32) {
        int s = 0;
        int q0 = tid * 32;
        #pragma unroll
        for (int q = 0; q < 32; q++) {
            int k = q0 + q;
            if (k < NBUCK) s += hist[k];
        }
        int x = s;
        #pragma unroll
        for (int d = 1; d < 32; d <<= 1) {
            int v = __shfl_up_sync(0xffffffffu, x, d);
            if (tid >= d) x += v;
        }
        segbase[tid] = x - s;
        if (tid == 31) segbase[32] = x;
    }
    __syncthreads();
    for (int k = tid; k < NBUCK; k += TPB) {
        int s = segbase[k >> 5];
        for (int q = k & ~31; q < k; q++) s += hist[q];
        base[k] = s;
        cur[k]  = s;
    }
    if (tid == 0) base[NBUCK] = segbase[32];
    __syncthreads();

    // ---- phase B: finalize entries (pre-scaled by a2) ----
    #pragma unroll
    for (int it = 0; it < AITER; it++) {
        int c = it * TPB + tid;
        if (c >= NIMG) break;
        float2 E = sCache[c];
        float delay = E.x, amp = E.y;
        if (amp < 0.0f) continue;              // culled (di > DIMAX)
        float dif = ceilf(delay);
        int   di  = (int)dif;
        float frac = __fsub_rn(dif, delay);
        if (frac == 0.0f) {                    // pure spike: sinc peak only
            if (di < RIR_LENGTH) {
                int sp = atomicAdd(&s_nsp, 1);
                if (sp < SPMAX) { s_spk_i[sp] = di; s_spk_a[sp] = amp; }
            }
            continue;
        }
        float a2 = 0.5f * INV_PI * amp * sinpif(frac);
        if (di & 1) a2 = -a2;                  // (-1)^di
        int dm = di % 80;
        float cD, sD;
        sincospif(((float)dm - frac) * 0.025f, &sD, &cD);
        int slot = atomicAdd(&cur[di >> BSH], 1);
        sEnt[slot] = make_float4(delay, a2, a2 * cD, a2 * sD);
        if (di < PAD) {                        // near-field: JAX wrap duplicate
            int w = atomicAdd(&s_nwr, 1);
            if (w < WMAX) {
                int dm2 = (dm + 48) % 80;      // (di + 3968) % 80
                float cW, sW;
                sincospif(((float)dm2 - frac) * 0.025f, &sW, &cW);
                s_wrap[2 * w + 0] = make_float4((float)(di + RIR_LENGTH), frac, a2, 0.f);
                s_wrap[2 * w + 1] = make_float4(cW, sW, 0.f, 0.f);
            }
        }
    }
    __syncthreads();

    // sentinel pad: overruns/prefetch read delay=1e9, coeffs=0 -> contribute 0
    {
        int ntot = base[NBUCK];
        for (int k = tid; k < EPAD; k += TPB)
            sEnt[ntot + k] = make_float4(1e9f, 0.f, 0.f, 0.f);
    }
    __syncthreads();

    // ---- phase D: gather, 8-lane groups, paired reciprocal, SW-pipelined ----
    int nsp = min(s_nsp, SPMAX);
    int nwr = min(s_nwr, WMAX);
    float* orir = out + b * RIR_LENGTH;

    #pragma unroll
    for (int m = 0; m < 4; m++) {
        int j      = m * TPB + tid;
        int wstart = m * TPB + (tid & ~31);
        bool act   = (j < RIR_LENGTH);         // warp-uniform (3968 % 32 == 0)

        int g8 = m * TPB + (tid & ~7);         // group base bin (8-bin window)
        float jf = (float)j;
        int jm = j % 80;
        float2 cs = sCS[jm];
        float cj = cs.x, sj = cs.y;
        float onej = (jm & 1) ? -1.f : 1.f;

        int lob = (g8 - 39) >> BSH; if (lob < 0) lob = 0;
        int hib = (g8 + 47) >> BSH; if (hib > NBUCK - 1) hib = NBUCK - 1;
        int elo = base[lob];
        int cnt = act ? (base[hib + 1] - elo) : 0;
        int mc  = __reduce_max_sync(0xffffffffu, cnt);

        const float4* p = sEnt + elo;
        float a0 = 0.f, a1 = 0.f;

        // software-pipelined double buffer (sentinel pad makes preload safe)
        float4 c0 = p[0], c1 = p[1], c2 = p[2], c3 = p[3];
        int it = 0;
        for (; it + 4 <= mc; it += 4) {
            // prefetch next iteration's entries while computing on current
            float4 n0 = p[it + 4], n1 = p[it + 5], n2 = p[it + 6], n3 = p[it + 7];
            // pair (c0, c1): one reciprocal
            float x0 = jf - c0.x;
            float x1 = jf - c1.x;
            float t0 = fmaf(cj, c0.z, c0.y);
            t0 = fmaf(sj, c0.w, t0);
            t0 = (fabsf(x0) < 40.f) ? t0 : 0.f;
            float t1 = fmaf(cj, c1.z, c1.y);
            t1 = fmaf(sj, c1.w, t1);
            t1 = (fabsf(x1) < 40.f) ? t1 : 0.f;
            float r01 = __fdividef(1.f, x0 * x1);
            a0 = fmaf(fmaf(t0, x1, t1 * x0), r01, a0);
            // pair (c2, c3): one reciprocal
            float x2 = jf - c2.x;
            float x3 = jf - c3.x;
            float t2 = fmaf(cj, c2.z, c2.y);
            t2 = fmaf(sj, c2.w, t2);
            t2 = (fabsf(x2) < 40.f) ? t2 : 0.f;
            float t3 = fmaf(cj, c3.z, c3.y);
            t3 = fmaf(sj, c3.w, t3);
            t3 = (fabsf(x3) < 40.f) ? t3 : 0.f;
            float r23 = __fdividef(1.f, x2 * x3);
            a1 = fmaf(fmaf(t2, x3, t3 * x2), r23, a1);
            c0 = n0; c1 = n1; c2 = n2; c3 = n3;
        }
        for (; it < mc; it++) {
            float4 E0 = p[it];
            float x = jf - E0.x;
            float t = fmaf(cj, E0.z, E0.y);
            t = fmaf(sj, E0.w, t);
            t = (fabsf(x) < 40.f) ? t : 0.f;
            a0 = fmaf(t, __fdividef(1.f, x), a0);
        }
        float acc = a0 + a1;

        // wrapped near-field taps land only in bins [3928, 3967]
        if (act && wstart + 31 >= RIR_LENGTH - PAD) {
            for (int w = 0; w < nwr; w++) {
                float4 A = s_wrap[2 * w], B = s_wrap[2 * w + 1];
                float x = (jf - A.x) + A.y;    // exact: int diff + frac
                float t = fmaf(cj, B.x, 1.f);
                t = fmaf(sj, B.y, t);
                t = (fabsf(x) < 40.f) ? t : 0.f;
                acc = fmaf(A.z * t, __fdividef(1.f, x), acc);
            }
        }
        acc *= onej;                           // deferred (-1)^j
        // spikes (rare)
        for (int sp = 0; sp < nsp; sp++)
            if (s_spk_i[sp] == j) acc += s_spk_a[sp];

        if (act) orir[j] = acc;
    }
}

// ---------------------------------------------------------------------------
extern "C" void kernel_launch(void* const* d_in, const int* in_sizes, int n_in,
                              void* d_out, int out_size) {
    const float* inp = (const float*)d_in[0];
    float* out = (float*)d_out;

    const int dynbytes = (MAXE + EPAD) * (int)sizeof(float4)
                       + MAXE * (int)sizeof(float2);          // 128,000
    cudaFuncSetAttribute(k_all, cudaFuncAttributeMaxDynamicSharedMemorySize, dynbytes);
    k_build_xyz<<<(GRID_TOT + 255) / 256, 256>>>();
    k_all<<<BATCH, TPB, dynbytes>>>(inp, out);
}